// round 17
// baseline (speedup 1.0000x reference)
#include <cuda_runtime.h>
#include <cuda_fp16.h>
#include <math.h>
#include <stdint.h>

// Problem constants
#define L_SEQ   2048
#define DM      1024
#define DI      1024
#define DTR     64
#define DS      16
#define PROJ    (DTR + 2 * DI * DS)   // 32832
#define BCW     32768                 // compact B/C width = 256 * 128
#define KDIM    1024

// -------- scratch (static device globals; no allocation) --------
__device__ __half g_bch[(size_t)L_SEQ * BCW];       // [B | C] per row, fp16
__device__ float  g_dlr[(size_t)L_SEQ * DTR];       // exact fp32 delta_lr
__device__ float  g_delta[(size_t)L_SEQ * DI];
__device__ __half g_xf[(size_t)L_SEQ * DM];
__device__ __half g_wf[(size_t)BCW * DM];           // W_in rows 64..32831
__device__ __half g_wof[(size_t)DM * DI];
__device__ __half g_yf[(size_t)L_SEQ * DI];
// two-pass scan intermediates: 16 chunks x 16384 (d,s) lanes
#define NCHK 16
#define CHK  (L_SEQ / NCHK)          // 128
__device__ float g_hp[NCHK * 16384];
__device__ float g_ap[NCHK * 16384];
__device__ float g_hin[NCHK * 16384];

// ============================================================================
// helpers
// ============================================================================
__device__ __forceinline__ uint32_t smem_u32(const void* p) {
    uint32_t a;
    asm("{ .reg .u64 t; cvta.to.shared.u64 t, %1; cvt.u32.u64 %0, t; }" : "=r"(a) : "l"(p));
    return a;
}
__device__ __forceinline__ uint32_t swz128(uint32_t o) { return o ^ ((o >> 3) & 0x70); }

__device__ __forceinline__ void cp_async16(uint32_t dst, const void* src) {
    asm volatile("cp.async.cg.shared.global [%0], [%1], 16;" :: "r"(dst), "l"(src));
}
#define CP_COMMIT() asm volatile("cp.async.commit_group;" ::: "memory")
#define CP_WAIT(n)  asm volatile("cp.async.wait_group %0;" :: "n"(n) : "memory")

__device__ __forceinline__ void ldsm4(uint32_t* r, uint32_t addr) {
    asm volatile("ldmatrix.sync.aligned.m8n8.x4.shared.b16 {%0,%1,%2,%3}, [%4];"
        : "=r"(r[0]), "=r"(r[1]), "=r"(r[2]), "=r"(r[3]) : "r"(addr));
}
__device__ __forceinline__ void mma_f16(float* d, const uint32_t* a, const uint32_t* b) {
    asm volatile(
        "mma.sync.aligned.m16n8k16.row.col.f32.f16.f16.f32 "
        "{%0,%1,%2,%3}, {%4,%5,%6,%7}, {%8,%9}, {%0,%1,%2,%3};"
        : "+f"(d[0]), "+f"(d[1]), "+f"(d[2]), "+f"(d[3])
        : "r"(a[0]), "r"(a[1]), "r"(a[2]), "r"(a[3]), "r"(b[0]), "r"(b[1]));
}

// ============================================================================
// Kernel A: fused conversion (x, W_in[64:], W_out -> fp16) + exact fp32 dlr.
// cvt blocks [0, NCVTB) stream-convert; blocks [NCVTB, NCVTB+128) run dlr
// concurrently under cvt's DRAM traffic.
// ============================================================================
#define NX8   ((size_t)L_SEQ * DM / 8)
#define NW8   ((size_t)BCW * DM / 8)
#define NWO8  ((size_t)DM * DI / 8)
#define NALL8 (NX8 + NW8 + NWO8)
#define NCVTB ((unsigned)((NALL8 + 255) / 256))
#define NDLRB (L_SEQ / 16)           // 128

__global__ __launch_bounds__(256) void cvt_dlr_kernel(
    const float* __restrict__ x, const float* __restrict__ W_in,
    const float* __restrict__ W_out)
{
    __shared__ float sx[64][17];
    __shared__ float sw[64][65];
    const int tid = threadIdx.x;

    if (blockIdx.x < NCVTB) {
        // ---- cvt path: 8 floats/thread, single STG.128 ----
        size_t q = (size_t)blockIdx.x * 256 + tid;
        if (q >= NALL8) return;
        const float* src;
        __half* dst;
        size_t i;
        if (q < NX8) { i = q * 8; src = x; dst = g_xf; }
        else if (q < NX8 + NW8) { i = (q - NX8) * 8; src = W_in + (size_t)DTR * DM; dst = g_wf; }
        else { i = (q - NX8 - NW8) * 8; src = W_out; dst = g_wof; }
        float4 v0 = *(const float4*)(src + i);
        float4 v1 = *(const float4*)(src + i + 4);
        __half2 h0 = __floats2half2_rn(v0.x, v0.y);
        __half2 h1 = __floats2half2_rn(v0.z, v0.w);
        __half2 h2 = __floats2half2_rn(v1.x, v1.y);
        __half2 h3 = __floats2half2_rn(v1.z, v1.w);
        uint4 pk;
        pk.x = *(uint32_t*)&h0; pk.y = *(uint32_t*)&h1;
        pk.z = *(uint32_t*)&h2; pk.w = *(uint32_t*)&h3;
        *(uint4*)(dst + i) = pk;
        return;
    }

    // ---- dlr path: dlr[t,k] = x[t,:]·W_in[k,:], 16 t-rows per block ----
    const int blk = blockIdx.x - NCVTB;
    const int k = tid & 63;
    const int tg = tid >> 6;
    const int t0 = blk * 16;

    float acc[4];
    #pragma unroll
    for (int i = 0; i < 4; i++) acc[i] = 0.f;

    for (int kc = 0; kc < 16; kc++) {
        {
            const int t = tid >> 4, c = tid & 15;
            float4 v = *(const float4*)(x + (size_t)(t0 + t) * KDIM + kc * 64 + c * 4);
            sx[c * 4 + 0][t] = v.x; sx[c * 4 + 1][t] = v.y;
            sx[c * 4 + 2][t] = v.z; sx[c * 4 + 3][t] = v.w;
        }
        #pragma unroll
        for (int j = 0; j < 4; j++) {
            const int q = tid * 4 + j;
            const int k2 = q >> 4, c = q & 15;
            float4 v = *(const float4*)(W_in + (size_t)k2 * KDIM + kc * 64 + c * 4);
            sw[c * 4 + 0][k2] = v.x; sw[c * 4 + 1][k2] = v.y;
            sw[c * 4 + 2][k2] = v.z; sw[c * 4 + 3][k2] = v.w;
        }
        __syncthreads();
        #pragma unroll 16
        for (int kk = 0; kk < 64; kk++) {
            const float w = sw[kk][k];
            #pragma unroll
            for (int i = 0; i < 4; i++)
                acc[i] = fmaf(sx[kk][tg * 4 + i], w, acc[i]);
        }
        __syncthreads();
    }
    #pragma unroll
    for (int i = 0; i < 4; i++)
        g_dlr[(size_t)(t0 + tg * 4 + i) * DTR + k] = acc[i];
}

// ============================================================================
// delta block (device fn, 512 threads, dynamic smem):
// delta[t,d] = softplus(g_dlr[t,:]·W_delta[d,:]); t-tile 64, d-tile 128.
// ============================================================================
__device__ void delta_block(char* smem, const float* __restrict__ W_delta,
                            int dblk, int tid)
{
    float* sdl = (float*)smem;                 // [64][64]
    float* swt = (float*)(smem + 16384);       // [64][129]
    const int t0 = (dblk >> 3) * 64;
    const int d0 = (dblk & 7) * 128;

    // dlr tile: 64 t x 64 kk = 1024 float4, 2 per thread
    #pragma unroll
    for (int j = 0; j < 2; j++) {
        const int q = tid * 2 + j;             // 0..1023
        const int t = q >> 4, c = q & 15;
        float4 v = *(const float4*)(g_dlr + (size_t)(t0 + t) * DTR + c * 4);
        *(float4*)&sdl[t * 64 + c * 4] = v;
    }
    // W tile: 128 d x 64 kk = 2048 float4, 4 per thread (transpose)
    #pragma unroll
    for (int j = 0; j < 4; j++) {
        const int q = tid * 4 + j;             // 0..2047
        const int d = q >> 4, c = q & 15;
        float4 v = *(const float4*)(W_delta + (size_t)(d0 + d) * DTR + c * 4);
        swt[(c * 4 + 0) * 129 + d] = v.x; swt[(c * 4 + 1) * 129 + d] = v.y;
        swt[(c * 4 + 2) * 129 + d] = v.z; swt[(c * 4 + 3) * 129 + d] = v.w;
    }
    __syncthreads();

    const int d = tid & 127, tg = tid >> 7;    // 4 t-groups of 16
    float accv[16];
    #pragma unroll
    for (int t = 0; t < 16; t++) accv[t] = 0.f;

    #pragma unroll 4
    for (int k4 = 0; k4 < 16; k4++) {
        const float w0 = swt[(k4 * 4 + 0) * 129 + d];
        const float w1 = swt[(k4 * 4 + 1) * 129 + d];
        const float w2 = swt[(k4 * 4 + 2) * 129 + d];
        const float w3 = swt[(k4 * 4 + 3) * 129 + d];
        #pragma unroll
        for (int t = 0; t < 16; t++) {
            const float4 dl = *(const float4*)&sdl[(tg * 16 + t) * 64 + k4 * 4];
            float a = fmaf(dl.x, w0, accv[t]);
            a = fmaf(dl.y, w1, a);
            a = fmaf(dl.z, w2, a);
            accv[t] = fmaf(dl.w, w3, a);
        }
    }
    #pragma unroll
    for (int t = 0; t < 16; t++) {
        const float z = accv[t];
        const float sp = fmaxf(z, 0.f) + log1pf(__expf(-fabsf(z)));
        g_delta[(size_t)(t0 + tg * 16 + t) * DI + d0 + d] = sp;
    }
}

// ============================================================================
// FP16 GEMM (+optional fused delta blocks at blockIdx.y >= ny):
// CTA 128x128, BK=64, 512 thr, 2 CTAs/SM, per-warp ks rotation,
// 3-stage cp.async pipeline, guard-free epilogue.
// ============================================================================
#define F_ATILE  16384
#define F_STAGE  32768
#define F_NSTAGE 3
#define SMEM_F16_TOTAL (F_NSTAGE * F_STAGE)   // 96 KB
#define F_NKC    (KDIM / 64)        // 16

template<typename OT>
__global__ __launch_bounds__(512, 2) void gemm_f16(
    const __half* __restrict__ A, const __half* __restrict__ B,
    OT* __restrict__ C, int ldc, const float* __restrict__ W_delta, int ny)
{
    extern __shared__ char smem[];
    const int tid = threadIdx.x;

    if ((int)blockIdx.y >= ny) {
        delta_block(smem, W_delta, ((int)blockIdx.y - ny) * (int)gridDim.x + (int)blockIdx.x, tid);
        return;
    }

    const uint32_t sbase = smem_u32(smem);
    const int wid = tid >> 5, lane = tid & 31;
    const int wm = wid & 3, wn = wid >> 2;

    const int m0 = blockIdx.x * 128;
    const int n0 = blockIdx.y * 128;

    float acc[2][4][4];
    #pragma unroll
    for (int i = 0; i < 2; i++)
        #pragma unroll
        for (int j = 0; j < 4; j++)
            #pragma unroll
            for (int q = 0; q < 4; q++) acc[i][j][q] = 0.f;

    auto issue = [&](int kc) {
        if (kc < F_NKC) {
            const uint32_t soff = sbase + (kc % F_NSTAGE) * F_STAGE;
            #pragma unroll
            for (int j = 0; j < 2; j++) {
                const int q = tid * 2 + j;
                const int row = q >> 3, c = q & 7;
                const uint32_t so = swz128((uint32_t)(row * 128 + c * 16));
                const size_t ga = (size_t)(m0 + row) * KDIM + (size_t)kc * 64 + c * 8;
                const size_t gb = (size_t)(n0 + row) * KDIM + (size_t)kc * 64 + c * 8;
                cp_async16(soff + so, A + ga);
                cp_async16(soff + F_ATILE + so, B + gb);
            }
        }
        CP_COMMIT();
    };

    const int rb_base = wn * 32 + ((lane >> 4) << 3) + (lane & 7);
    const int cb_half = (lane >> 3) & 1;
    const int ra_base = wm * 32 + (lane & 15);
    const int ca_half = lane >> 4;
    const int ksr = wn;

    issue(0);
    issue(1);

    #pragma unroll 1
    for (int kc = 0; kc < F_NKC; kc++) {
        if (kc + 1 < F_NKC) CP_WAIT(1); else CP_WAIT(0);
        __syncthreads();
        issue(kc + 2);

        const uint32_t sA = sbase + (kc % F_NSTAGE) * F_STAGE;

        #pragma unroll
        for (int kss = 0; kss < 4; kss++) {
            const int ks = (kss + ksr) & 3;
            uint32_t bf[4][2];
            #pragma unroll
            for (int p = 0; p < 2; p++) {
                const int rowb = rb_base + p * 16;
                const int chb  = ks * 2 + cb_half;
                ldsm4(&bf[p * 2][0],
                      sA + F_ATILE + swz128((uint32_t)(rowb * 128 + chb * 16)));
            }
            #pragma unroll
            for (int mf = 0; mf < 2; mf++) {
                const int rowa = ra_base + mf * 16;
                const int cha  = ks * 2 + ca_half;
                uint32_t af[4];
                ldsm4(af, sA + swz128((uint32_t)(rowa * 128 + cha * 16)));
                #pragma unroll
                for (int nf = 0; nf < 4; nf++) mma_f16(acc[mf][nf], af, bf[nf]);
            }
        }
    }

    const int g = lane >> 2, t4 = lane & 3;
    #pragma unroll
    for (int mf = 0; mf < 2; mf++) {
        #pragma unroll
        for (int nf = 0; nf < 4; nf++) {
            const int m = m0 + wm * 32 + mf * 16 + g;
            const int n = n0 + wn * 32 + nf * 8 + t4 * 2;
            if constexpr (sizeof(OT) == 2) {
                *(__half2*)((__half*)C + (size_t)m * ldc + n) =
                    __floats2half2_rn(acc[mf][nf][0], acc[mf][nf][1]);
                *(__half2*)((__half*)C + (size_t)(m + 8) * ldc + n) =
                    __floats2half2_rn(acc[mf][nf][2], acc[mf][nf][3]);
            } else {
                *(float2*)((float*)C + (size_t)m * ldc + n) =
                    make_float2(acc[mf][nf][0], acc[mf][nf][1]);
                *(float2*)((float*)C + (size_t)(m + 8) * ldc + n) =
                    make_float2(acc[mf][nf][2], acc[mf][nf][3]);
            }
        }
    }
}

// ============================================================================
// Two-pass chunked scan (unchanged).
// ============================================================================
#define SC_T      32
#define SC_BBYTES (SC_T * 256)
#define SC_DBYTES (SC_T * 32)
#define A_D_OFF   SC_BBYTES
#define A_X_OFF   (SC_BBYTES + SC_DBYTES)
#define A_STAGE   (SC_BBYTES + 2 * SC_DBYTES)
#define SMEM_SCANA_TOTAL (4 * A_STAGE)
#define B_C_OFF   SC_BBYTES
#define B_D_OFF   (2 * SC_BBYTES)
#define B_X_OFF   (2 * SC_BBYTES + SC_DBYTES)
#define B_STAGE   (2 * SC_BBYTES + 2 * SC_DBYTES)
#define SMEM_SCANB_TOTAL (4 * B_STAGE)

__global__ __launch_bounds__(128) void scan_a_kernel(
    const float* __restrict__ x, const float* __restrict__ A_log)
{
    extern __shared__ char smem[];
    const uint32_t sbase = smem_u32(smem);
    const int tid = threadIdx.x;
    const int blk = blockIdx.x;
    const int c   = blockIdx.y;
    const int lc = tid >> 4, s = tid & 15;
    const int d = blk * 8 + lc;
    const float a = -expf(A_log[d * DS + s]);
    const size_t tb = (size_t)c * CHK;

    const char* gB = (const char*)(g_bch + (size_t)blk * 128);
    const char* gD = (const char*)(g_delta + (size_t)blk * 8);
    const char* gX = (const char*)(x + (size_t)blk * 8);

    #pragma unroll
    for (int st = 0; st < 4; st++) {
        const uint32_t soff = sbase + st * A_STAGE;
        const size_t t0 = tb + (size_t)st * SC_T;
        #pragma unroll
        for (int j = 0; j < 4; j++) {
            const int q = tid * 4 + j;
            const int stp = q >> 4, off = (q & 15) * 16;
            cp_async16(soff + stp * 256 + off, gB + (t0 + stp) * (BCW * 2) + off);
        }
        {
            const int q = tid & 63;
            const int stp = q >> 1, off = (q & 1) * 16;
            if (tid < 64)
                cp_async16(soff + A_D_OFF + stp * 32 + off, gD + (t0 + stp) * (DI * 4) + off);
            else
                cp_async16(soff + A_X_OFF + stp * 32 + off, gX + (t0 + stp) * (DI * 4) + off);
        }
        CP_COMMIT();
    }

    float h = 0.f, sdt = 0.f;
    #pragma unroll
    for (int st = 0; st < 4; st++) {
        switch (st) {
            case 0: CP_WAIT(3); break;
            case 1: CP_WAIT(2); break;
            case 2: CP_WAIT(1); break;
            default: CP_WAIT(0); break;
        }
        __syncthreads();
        const uint32_t so = st * A_STAGE;
        const __half* sB = (const __half*)(smem + so);
        const float* sD  = (const float*)(smem + so + A_D_OFF);
        const float* sX  = (const float*)(smem + so + A_X_OFF);
        #pragma unroll 8
        for (int stp = 0; stp < SC_T; stp++) {
            const float Bv = __half2float(sB[stp * 128 + tid]);
            const float dt = sD[stp * 8 + lc];
            const float xt = sX[stp * 8 + lc];
            h = fmaf(__expf(dt * a), h, dt * xt * Bv);
            sdt += dt;
        }
    }
    const int i = blk * 128 + tid;
    g_hp[c * 16384 + i] = h;
    g_ap[c * 16384 + i] = __expf(a * sdt);
}

__global__ __launch_bounds__(128) void scan_combine_kernel()
{
    const int i = blockIdx.x * 128 + threadIdx.x;
    float hp[NCHK], ap[NCHK];
    #pragma unroll
    for (int cc = 0; cc < NCHK; cc++) {
        hp[cc] = g_hp[cc * 16384 + i];
        ap[cc] = g_ap[cc * 16384 + i];
    }
    float hin = 0.f;
    #pragma unroll
    for (int cc = 0; cc < NCHK; cc++) {
        g_hin[cc * 16384 + i] = hin;
        hin = fmaf(ap[cc], hin, hp[cc]);
    }
}

__global__ __launch_bounds__(128) void scan_b_kernel(
    const float* __restrict__ x, const float* __restrict__ A_log,
    const float* __restrict__ Dv)
{
    extern __shared__ char smem[];
    const uint32_t sbase = smem_u32(smem);
    const int tid = threadIdx.x;
    const int blk = blockIdx.x;
    const int c   = blockIdx.y;
    const int lc = tid >> 4, s = tid & 15;
    const int d = blk * 8 + lc;
    const float a = -expf(A_log[d * DS + s]);
    const float Dd = Dv[d];
    const size_t tb = (size_t)c * CHK;

    const char* gB = (const char*)(g_bch + (size_t)blk * 128);
    const char* gC = (const char*)(g_bch + (size_t)DI * DS + (size_t)blk * 128);
    const char* gD = (const char*)(g_delta + (size_t)blk * 8);
    const char* gX = (const char*)(x + (size_t)blk * 8);

    #pragma unroll
    for (int st = 0; st < 4; st++) {
        const uint32_t soff = sbase + st * B_STAGE;
        const size_t t0 = tb + (size_t)st * SC_T;
        #pragma unroll
        for (int j = 0; j < 4; j++) {
            const int q = tid * 4 + j;
            const int stp = q >> 4, off = (q & 15) * 16;
            cp_async16(soff + stp * 256 + off, gB + (t0 + stp) * (BCW * 2) + off);
            cp_async16(soff + B_C_OFF + stp * 256 + off, gC + (t0 + stp) * (BCW * 2) + off);
        }
        {
            const int q = tid & 63;
            const int stp = q >> 1, off = (q & 1) * 16;
            if (tid < 64)
                cp_async16(soff + B_D_OFF + stp * 32 + off, gD + (t0 + stp) * (DI * 4) + off);
            else
                cp_async16(soff + B_X_OFF + stp * 32 + off, gX + (t0 + stp) * (DI * 4) + off);
        }
        CP_COMMIT();
    }

    float h = g_hin[c * 16384 + blk * 128 + tid];
    #pragma unroll
    for (int st = 0; st < 4; st++) {
        switch (st) {
            case 0: CP_WAIT(3); break;
            case 1: CP_WAIT(2); break;
            case 2: CP_WAIT(1); break;
            default: CP_WAIT(0); break;
        }
        __syncthreads();
        const uint32_t so = st * B_STAGE;
        const __half* sB = (const __half*)(smem + so);
        const __half* sC = (const __half*)(smem + so + B_C_OFF);
        const float* sD  = (const float*)(smem + so + B_D_OFF);
        const float* sX  = (const float*)(smem + so + B_X_OFF);
        const int tbase = (int)tb + st * SC_T;
        #pragma unroll 8
        for (int stp = 0; stp < SC_T; stp++) {
            const float Bv = __half2float(sB[stp * 128 + tid]);
            const float Cv = __half2float(sC[stp * 128 + tid]);
            const float dt = sD[stp * 8 + lc];
            const float xt = sX[stp * 8 + lc];
            h = fmaf(__expf(dt * a), h, dt * xt * Bv);
            float yv = h * Cv;
            yv += __shfl_xor_sync(0xffffffffu, yv, 1);
            yv += __shfl_xor_sync(0xffffffffu, yv, 2);
            yv += __shfl_xor_sync(0xffffffffu, yv, 4);
            yv += __shfl_xor_sync(0xffffffffu, yv, 8);
            if (s == 0)
                g_yf[(size_t)(tbase + stp) * DI + d] =
                    __float2half_rn(fmaf(xt, Dd, yv));
        }
    }
}

// ============================================================================
// Launch
// ============================================================================
extern "C" void kernel_launch(void* const* d_in, const int* in_sizes, int n_in,
                              void* d_out, int out_size)
{
    const float* x       = (const float*)d_in[0];
    const float* W_in    = (const float*)d_in[1];
    const float* W_delta = (const float*)d_in[2];
    const float* A_log   = (const float*)d_in[3];
    const float* Dv      = (const float*)d_in[4];
    const float* W_out   = (const float*)d_in[5];
    float* out = (float*)d_out;

    __half *bch, *xf, *wf, *wof, *yf;
    cudaGetSymbolAddress((void**)&bch, g_bch);
    cudaGetSymbolAddress((void**)&xf, g_xf);
    cudaGetSymbolAddress((void**)&wf, g_wf);
    cudaGetSymbolAddress((void**)&wof, g_wof);
    cudaGetSymbolAddress((void**)&yf, g_yf);

    cudaFuncSetAttribute(gemm_f16<__half>, cudaFuncAttributeMaxDynamicSharedMemorySize,
                         SMEM_F16_TOTAL);
    cudaFuncSetAttribute(gemm_f16<float>, cudaFuncAttributeMaxDynamicSharedMemorySize,
                         SMEM_F16_TOTAL);
    cudaFuncSetAttribute(scan_a_kernel, cudaFuncAttributeMaxDynamicSharedMemorySize,
                         SMEM_SCANA_TOTAL);
    cudaFuncSetAttribute(scan_b_kernel, cudaFuncAttributeMaxDynamicSharedMemorySize,
                         SMEM_SCANB_TOTAL);

    // 1) fused conversions + exact fp32 dlr (concurrent)
    cvt_dlr_kernel<<<NCVTB + NDLRB, 256>>>(x, W_in, W_out);
    // 2) B/C GEMM with delta blocks fused into the tail wave
    {
        dim3 grid(L_SEQ / 128, BCW / 128 + 16);   // 16 x (256 gemm + 16 delta rows)
        gemm_f16<__half><<<grid, 512, SMEM_F16_TOTAL>>>(xf, wf, bch, BCW, W_delta, BCW / 128);
    }
    // 3) two-pass chunked scan
    {
        dim3 ga(128, NCHK);
        scan_a_kernel<<<ga, 128, SMEM_SCANA_TOTAL>>>(x, A_log);
        scan_combine_kernel<<<128, 128>>>();
        scan_b_kernel<<<ga, 128, SMEM_SCANB_TOTAL>>>(x, A_log, Dv);
    }
    // 4) out = y @ W_out^T  -> f32 output (no delta blocks: ny > grid.y)
    {
        dim3 grid(L_SEQ / 128, DM / 128);
        gemm_f16<float><<<grid, 512, SMEM_F16_TOTAL>>>(yf, wof, out, DM, nullptr, 1 << 20);
    }
}